// round 7
// baseline (speedup 1.0000x reference)
#include <cuda_runtime.h>
#include <cuda_fp16.h>
#include <mma.h>
#include <cstdint>
#include <cstddef>

using namespace nvcuda;

#define E_ 8
#define T_ 1024
#define D_ 2048
#define H_ 5632

// fp16 copies of all GEMM operands (filled every call) + fp16 y scratch
__device__ __align__(256) __half g_hx [(size_t)E_ * T_ * D_];
__device__ __align__(256) __half g_hw1[(size_t)E_ * D_ * H_];
__device__ __align__(256) __half g_hw2[(size_t)E_ * D_ * H_];
__device__ __align__(256) __half g_hw3[(size_t)E_ * H_ * D_];
__device__ __align__(256) __half g_hy [(size_t)E_ * T_ * H_];

// ---------------- helpers ----------------
union Pack4 { uint2 u; __half2 h[2]; };
__device__ __forceinline__ uint2 pack4(float4 v) {
    Pack4 p;
    p.h[0] = __floats2half2_rn(v.x, v.y);
    p.h[1] = __floats2half2_rn(v.z, v.w);
    return p.u;
}
__device__ __forceinline__ float silu_mul(float v1, float v2) {
    return v2 * v1 * (1.0f / (1.0f + __expf(-v1)));
}
__device__ __forceinline__ void cp_async16(void* s, const void* g) {
    uint32_t sa = (uint32_t)__cvta_generic_to_shared(s);
    asm volatile("cp.async.cg.shared.global [%0], [%1], 16;" :: "r"(sa), "l"(g));
}
__device__ __forceinline__ void cp_commit() { asm volatile("cp.async.commit_group;"); }
template <int N>
__device__ __forceinline__ void cp_wait() { asm volatile("cp.async.wait_group %0;" :: "n"(N)); }

// ---------------- fp32 -> fp16 streaming conversion ----------------
// NOTE: destination globals are referenced in DEVICE code (template-selected).
// Passing a __device__ symbol as a host-side kernel arg is invalid (R6 bug).
constexpr size_t XC = (size_t)E_ * T_ * D_ / 4;   // float4 chunks
constexpr size_t WC = (size_t)E_ * D_ * H_ / 4;

template <int SEL>
__global__ void __launch_bounds__(256)
cvt_one(const float* __restrict__ src, size_t n4)
{
    size_t i = (size_t)blockIdx.x * blockDim.x + threadIdx.x;
    if (i >= n4) return;
    __half* dst;
    if constexpr (SEL == 0) dst = g_hx;
    else if constexpr (SEL == 1) dst = g_hw1;
    else if constexpr (SEL == 2) dst = g_hw2;
    else dst = g_hw3;
    ((uint2*)dst)[i] = pack4(((const float4*)src)[i]);
}

// ---------------- tiling ----------------
constexpr int BM  = 256;
constexpr int BK  = 64;
constexpr int BN1 = 64;    // kernel1: N per gate matrix (per CTA)
constexpr int BN2 = 128;   // kernel2: N tile
constexpr int LDA  = BK  + 8;   // 72 halfs (144B rows)
constexpr int LDB1 = BN1 + 8;   // 72
constexpr int LDB2 = BN2 + 8;   // 136
constexpr int STG = 4;

constexpr int A_SLAB  = BM * LDA;    // 18432 halfs
constexpr int B1_SLAB = BK * LDB1;   // 4608
constexpr int B2_SLAB = BK * LDB2;   // 8704

constexpr size_t SMEM1 = (size_t)STG * (A_SLAB + 2 * B1_SLAB) * sizeof(__half); // 221184
constexpr size_t SMEM2 = (size_t)STG * (A_SLAB + B2_SLAB) * sizeof(__half);     // 217088

// =====================================================================
// Kernel 1: y = silu(x@W1) * (x@W2)
// 512 threads, 16 warps (4M x 4N). Warp tile: 64 x 16 per gate (A reused).
// Grid: (T/BM, H/BN1, E) = (4, 88, 8)  -- M fastest for L2 weight reuse
// =====================================================================
__global__ void __launch_bounds__(512, 1)
ffn_gate_h()
{
    extern __shared__ __align__(128) __half smem[];
    __half* sA  = smem;                    // [STG][A_SLAB]
    __half* sB1 = sA  + STG * A_SLAB;      // [STG][B1_SLAB]
    __half* sB2 = sB1 + STG * B1_SLAB;     // [STG][B1_SLAB]

    const int tid  = threadIdx.x;
    const int warp = tid >> 5;
    const int lane = tid & 31;
    const int wm   = warp >> 2;   // 0..3
    const int wn   = warp & 3;    // 0..3
    const int e  = blockIdx.z;
    const int m0 = blockIdx.x * BM;
    const int n0 = blockIdx.y * BN1;
    const __half* Ax  = g_hx  + (size_t)e * T_ * D_;
    const __half* B1g = g_hw1 + (size_t)e * D_ * H_;
    const __half* B2g = g_hw2 + (size_t)e * D_ * H_;

    wmma::fragment<wmma::accumulator, 16, 16, 16, float> c1[4], c2[4];
    #pragma unroll
    for (int i = 0; i < 4; i++) {
        wmma::fill_fragment(c1[i], 0.0f);
        wmma::fill_fragment(c2[i], 0.0f);
    }

    auto load = [&](int s, int kt) {
        const int k0 = kt * BK;
        // A: 256 rows x 8 chunks(16B) = 2048 -> 4/thread
        #pragma unroll
        for (int i = 0; i < 4; i++) {
            int u = tid + i * 512;
            int row = u >> 3, ch = u & 7;
            cp_async16(sA + s * A_SLAB + row * LDA + ch * 8,
                       Ax + (size_t)(m0 + row) * D_ + k0 + ch * 8);
        }
        // B1+B2: 2 x 64 rows x 8 chunks = 1024 -> 2/thread
        #pragma unroll
        for (int i = 0; i < 2; i++) {
            int u = tid + i * 512;
            int mat = u >> 9;
            int rem = u & 511;
            int r = rem >> 3, ch = rem & 7;
            const __half* src = (mat ? B2g : B1g) + (size_t)(k0 + r) * H_ + n0 + ch * 8;
            __half* dst = (mat ? sB2 : sB1) + s * B1_SLAB + r * LDB1 + ch * 8;
            cp_async16(dst, src);
        }
        cp_commit();
    };

    constexpr int NK = D_ / BK;  // 32
    load(0, 0);
    load(1, 1);
    load(2, 2);

    for (int kt = 0; kt < NK; kt++) {
        const int s = kt & 3;
        if (kt + 2 < NK) cp_wait<2>(); else cp_wait<0>();  // tail-safe drain
        __syncthreads();
        if (kt + 3 < NK) load((kt + 3) & 3, kt + 3);

        const __half* aW  = sA  + s * A_SLAB  + (wm * 64) * LDA;
        const __half* b1W = sB1 + s * B1_SLAB + wn * 16;
        const __half* b2W = sB2 + s * B1_SLAB + wn * 16;
        #pragma unroll
        for (int kk = 0; kk < BK / 16; kk++) {
            wmma::fragment<wmma::matrix_a, 16, 16, 16, __half, wmma::row_major> a[4];
            #pragma unroll
            for (int i = 0; i < 4; i++)
                wmma::load_matrix_sync(a[i], aW + i * 16 * LDA + kk * 16, LDA);
            {
                wmma::fragment<wmma::matrix_b, 16, 16, 16, __half, wmma::row_major> b;
                wmma::load_matrix_sync(b, b1W + kk * 16 * LDB1, LDB1);
                #pragma unroll
                for (int i = 0; i < 4; i++)
                    wmma::mma_sync(c1[i], a[i], b, c1[i]);
            }
            {
                wmma::fragment<wmma::matrix_b, 16, 16, 16, __half, wmma::row_major> b;
                wmma::load_matrix_sync(b, b2W + kk * 16 * LDB1, LDB1);
                #pragma unroll
                for (int i = 0; i < 4; i++)
                    wmma::mma_sync(c2[i], a[i], b, c2[i]);
            }
        }
        // no bottom barrier: next iteration's top sync orders stage reuse
    }

    // Epilogue: silu(c1)*c2 -> fp16 y. Per-warp 64x16 fp32 patch in smem.
    __syncthreads();
    float* pw = (float*)smem + warp * (64 * 16);
    #pragma unroll
    for (int i = 0; i < 4; i++) {
        #pragma unroll
        for (int t = 0; t < c1[i].num_elements; t++)
            c1[i].x[t] = silu_mul(c1[i].x[t], c2[i].x[t]);
        wmma::store_matrix_sync(pw + i * 16 * 16, c1[i], 16, wmma::mem_row_major);
    }
    __syncwarp();
    __half* yb = g_hy + (size_t)e * T_ * H_ + (size_t)(m0 + wm * 64) * H_ + n0 + wn * 16;
    #pragma unroll
    for (int i = 0; i < 16; i++) {
        int u = lane + i * 32;          // 0..511 over 64 rows x 8 half2-cols
        int row = u >> 3, col2 = u & 7;
        float2 v = *(float2*)(pw + row * 16 + col2 * 2);
        *(__half2*)(yb + (size_t)row * H_ + col2 * 2) = __floats2half2_rn(v.x, v.y);
    }
}

// =====================================================================
// Kernel 2: out = y @ W3
// 512 threads, 16 warps (4M x 4N). Warp tile 64x32.
// Grid: (T/BM, D/BN2, E) = (4, 16, 8)  -- M fastest for L2 weight reuse
// =====================================================================
__global__ void __launch_bounds__(512, 1)
ffn_down_h(float* __restrict__ Out)
{
    extern __shared__ __align__(128) __half smem[];
    __half* sA = smem;                 // [STG][A_SLAB]
    __half* sB = sA + STG * A_SLAB;    // [STG][B2_SLAB]

    const int tid  = threadIdx.x;
    const int warp = tid >> 5;
    const int wm   = warp >> 2;
    const int wn   = warp & 3;
    const int e  = blockIdx.z;
    const int m0 = blockIdx.x * BM;
    const int n0 = blockIdx.y * BN2;
    const __half* Ay = g_hy  + (size_t)e * T_ * H_;
    const __half* Bg = g_hw3 + (size_t)e * H_ * D_;

    wmma::fragment<wmma::accumulator, 16, 16, 16, float> c[4][2];
    #pragma unroll
    for (int i = 0; i < 4; i++)
        #pragma unroll
        for (int j = 0; j < 2; j++)
            wmma::fill_fragment(c[i][j], 0.0f);

    auto load = [&](int s, int kt) {
        const int k0 = kt * BK;
        #pragma unroll
        for (int i = 0; i < 4; i++) {
            int u = tid + i * 512;
            int row = u >> 3, ch = u & 7;
            cp_async16(sA + s * A_SLAB + row * LDA + ch * 8,
                       Ay + (size_t)(m0 + row) * H_ + k0 + ch * 8);
        }
        // B: 64 rows x 16 chunks = 1024 -> 2/thread
        #pragma unroll
        for (int i = 0; i < 2; i++) {
            int u = tid + i * 512;
            int r = u >> 4, ch = u & 15;
            cp_async16(sB + s * B2_SLAB + r * LDB2 + ch * 8,
                       Bg + (size_t)(k0 + r) * D_ + n0 + ch * 8);
        }
        cp_commit();
    };

    constexpr int NK = H_ / BK;  // 88
    load(0, 0);
    load(1, 1);
    load(2, 2);

    for (int kt = 0; kt < NK; kt++) {
        const int s = kt & 3;
        if (kt + 2 < NK) cp_wait<2>(); else cp_wait<0>();  // tail-safe drain
        __syncthreads();
        if (kt + 3 < NK) load((kt + 3) & 3, kt + 3);

        const __half* aW = sA + s * A_SLAB  + (wm * 64) * LDA;
        const __half* bW = sB + s * B2_SLAB + wn * 32;
        #pragma unroll
        for (int kk = 0; kk < BK / 16; kk++) {
            wmma::fragment<wmma::matrix_a, 16, 16, 16, __half, wmma::row_major> a[4];
            #pragma unroll
            for (int i = 0; i < 4; i++)
                wmma::load_matrix_sync(a[i], aW + i * 16 * LDA + kk * 16, LDA);
            wmma::fragment<wmma::matrix_b, 16, 16, 16, __half, wmma::row_major> b[2];
            #pragma unroll
            for (int j = 0; j < 2; j++)
                wmma::load_matrix_sync(b[j], bW + kk * 16 * LDB2 + j * 16, LDB2);
            #pragma unroll
            for (int i = 0; i < 4; i++)
                #pragma unroll
                for (int j = 0; j < 2; j++)
                    wmma::mma_sync(c[i][j], a[i], b[j], c[i][j]);
        }
        // no bottom barrier
    }

    #pragma unroll
    for (int i = 0; i < 4; i++)
        #pragma unroll
        for (int j = 0; j < 2; j++)
            wmma::store_matrix_sync(
                Out + (size_t)e * T_ * D_
                    + (size_t)(m0 + wm * 64 + i * 16) * D_ + (n0 + wn * 32 + j * 16),
                c[i][j], D_, wmma::mem_row_major);
}

// =====================================================================
extern "C" void kernel_launch(void* const* d_in, const int* in_sizes, int n_in,
                              void* d_out, int out_size)
{
    const float* x  = (const float*)d_in[0];
    const float* w1 = (const float*)d_in[1];
    const float* w2 = (const float*)d_in[2];
    const float* w3 = (const float*)d_in[3];
    float* out = (float*)d_out;
    (void)in_sizes; (void)n_in; (void)out_size;

    cudaFuncSetAttribute(ffn_gate_h, cudaFuncAttributeMaxDynamicSharedMemorySize, (int)SMEM1);
    cudaFuncSetAttribute(ffn_down_h, cudaFuncAttributeMaxDynamicSharedMemorySize, (int)SMEM2);

    // streaming fp32->fp16 conversions (dst selected in device code)
    cvt_one<0><<<(int)((XC + 255) / 256), 256>>>(x,  XC);
    cvt_one<1><<<(int)((WC + 255) / 256), 256>>>(w1, WC);
    cvt_one<2><<<(int)((WC + 255) / 256), 256>>>(w2, WC);
    cvt_one<3><<<(int)((WC + 255) / 256), 256>>>(w3, WC);

    dim3 g1(T_ / BM, H_ / BN1, E_);   // (4, 88, 8) -- M fastest
    ffn_gate_h<<<g1, 512, SMEM1>>>();

    dim3 g2(T_ / BM, D_ / BN2, E_);   // (4, 16, 8) -- M fastest
    ffn_down_h<<<g2, 512, SMEM2>>>(out);
}